// round 11
// baseline (speedup 1.0000x reference)
#include <cuda_runtime.h>
#include <math.h>

#define BSZ 4
#define NN 256
#define DXD 256
#define DFFD 1024
#define EPSV 1e-5f
#define MROWS (BSZ*NN)   // 1024

// ---------------- scratch (allocation-free) ----------------
__device__ __align__(16) float g_Q   [MROWS*DXD];
__device__ __align__(16) float g_K   [MROWS*DXD];
__device__ __align__(16) float g_V   [MROWS*DXD];
__device__ __align__(16) float g_att [MROWS*DXD];
__device__ __align__(16) float g_X1  [MROWS*DXD];
__device__ __align__(16) float g_ffn1[MROWS*DFFD];
__device__ __align__(16) float g_ffn2[MROWS*DXD];

__device__ __forceinline__ float* scratch_ptr(int id) {
    switch (id) {
        case 0: return g_Q;
        case 1: return g_K;
        case 2: return g_V;
        case 3: return g_att;
        case 5: return g_X1;
        case 6: return g_ffn1;
        default: return g_ffn2;
    }
}

// ---------------- tf32 / cp.async helpers ----------------
__device__ __forceinline__ unsigned f2tf32_u(float x) {
    unsigned r;
    asm("cvt.rna.tf32.f32 %0, %1;" : "=r"(r) : "f"(x));
    return r;
}

__device__ __forceinline__ void cp_async16(unsigned saddr, const void* gptr) {
    asm volatile("cp.async.ca.shared.global [%0], [%1], 16;" :: "r"(saddr), "l"(gptr));
}
#define CP_COMMIT() asm volatile("cp.async.commit_group;" ::: "memory")
#define CP_WAIT(n)  asm volatile("cp.async.wait_group %0;" :: "n"(n) : "memory")

__device__ __forceinline__ void mma_tf32(float& c0, float& c1, float& c2, float& c3,
                                         unsigned a0, unsigned a1, unsigned a2, unsigned a3,
                                         unsigned b0, unsigned b1)
{
    asm volatile(
        "mma.sync.aligned.m16n8k8.row.col.f32.tf32.tf32.f32 "
        "{%0,%1,%2,%3}, {%4,%5,%6,%7}, {%8,%9}, {%0,%1,%2,%3};"
        : "+f"(c0), "+f"(c1), "+f"(c2), "+f"(c3)
        : "r"(a0), "r"(a1), "r"(a2), "r"(a3), "r"(b0), "r"(b1));
}

// ---------------- tf32 GEMM, cp.async double-buffered, cvt at fragment load ----------------
#define SA 36
#define SB 68

template<int MT, int K>
__device__ __forceinline__ void pgemm_core(const float* __restrict__ A,
                                           const float* __restrict__ W,
                                           const float* __restrict__ bias,
                                           float* __restrict__ Out,
                                           int N, int act,
                                           const float* __restrict__ rowmask,
                                           int row0, int col0)
{
    constexpr int BM  = MT * 32;
    constexpr int AIT = BM / 32;
    constexpr int NK  = K / 32;

    __shared__ __align__(16) float As[2][BM][SA];
    __shared__ __align__(16) float Bs[2][32][SB];

    const int tid    = threadIdx.x;
    const int lane   = tid & 31;
    const int wid    = tid >> 5;
    const int warp_m = wid & 1;
    const int warp_n = wid >> 1;
    const int lr = lane >> 2;
    const int lc = lane & 3;

    int am_[AIT];
#pragma unroll
    for (int it = 0; it < AIT; it++) am_[it] = (tid + it * 256) >> 3;
    const int aq  = tid & 7;
    const int bk_[2] = { (tid + 0) >> 4, (tid + 256) >> 4 };
    const int bq  = tid & 15;

    unsigned sA[2][AIT], sB[2][2];
#pragma unroll
    for (int bf = 0; bf < 2; bf++) {
#pragma unroll
        for (int it = 0; it < AIT; it++)
            sA[bf][it] = (unsigned)__cvta_generic_to_shared(&As[bf][am_[it]][aq * 4]);
#pragma unroll
        for (int it = 0; it < 2; it++)
            sB[bf][it] = (unsigned)__cvta_generic_to_shared(&Bs[bf][bk_[it]][bq * 4]);
    }

#pragma unroll
    for (int it = 0; it < AIT; it++)
        cp_async16(sA[0][it], &A[(size_t)(row0 + am_[it]) * K + aq * 4]);
#pragma unroll
    for (int it = 0; it < 2; it++)
        cp_async16(sB[0][it], &W[(size_t)bk_[it] * N + col0 + bq * 4]);
    CP_COMMIT();

    float acc[MT][2][4];
#pragma unroll
    for (int mt = 0; mt < MT; mt++)
#pragma unroll
        for (int nt = 0; nt < 2; nt++)
#pragma unroll
            for (int i = 0; i < 4; i++) acc[mt][nt][i] = 0.f;

    int buf = 0;
#pragma unroll 2
    for (int ki = 0; ki < NK; ki++) {
        if (ki + 1 < NK) {
            const int kt = (ki + 1) * 32;
#pragma unroll
            for (int it = 0; it < AIT; it++)
                cp_async16(sA[buf ^ 1][it], &A[(size_t)(row0 + am_[it]) * K + kt + aq * 4]);
#pragma unroll
            for (int it = 0; it < 2; it++)
                cp_async16(sB[buf ^ 1][it], &W[(size_t)(kt + bk_[it]) * N + col0 + bq * 4]);
            CP_COMMIT();
            CP_WAIT(1);
        } else {
            CP_WAIT(0);
        }
        __syncthreads();

#pragma unroll
        for (int ks = 0; ks < 4; ks++) {
            const int k0 = ks * 8;
            unsigned b0[2], b1[2];
#pragma unroll
            for (int nt = 0; nt < 2; nt++) {
                const float* pb = &Bs[buf][k0 + lc][warp_n * 16 + nt * 8 + lr];
                b0[nt] = f2tf32_u(pb[0]);
                b1[nt] = f2tf32_u(pb[4 * SB]);
            }
#pragma unroll
            for (int mt = 0; mt < MT; mt++) {
                const float* pa = &As[buf][warp_m * (BM / 2) + mt * 16 + lr][k0 + lc];
                unsigned a0 = f2tf32_u(pa[0]);
                unsigned a1 = f2tf32_u(pa[8 * SA]);
                unsigned a2 = f2tf32_u(pa[4]);
                unsigned a3 = f2tf32_u(pa[8 * SA + 4]);
#pragma unroll
                for (int nt = 0; nt < 2; nt++)
                    mma_tf32(acc[mt][nt][0], acc[mt][nt][1], acc[mt][nt][2], acc[mt][nt][3],
                             a0, a1, a2, a3, b0[nt], b1[nt]);
            }
        }
        __syncthreads();
        buf ^= 1;
    }

#pragma unroll
    for (int mt = 0; mt < MT; mt++) {
#pragma unroll
        for (int nt = 0; nt < 2; nt++) {
            const int col = col0 + warp_n * 16 + nt * 8 + 2 * lc;
            const float bv0 = bias[col], bv1 = bias[col + 1];
#pragma unroll
            for (int h = 0; h < 2; h++) {
                const int row = row0 + warp_m * (BM / 2) + mt * 16 + lr + h * 8;
                const float rm = rowmask ? rowmask[row] : 1.f;
                float v0 = acc[mt][nt][2 * h + 0] + bv0;
                float v1 = acc[mt][nt][2 * h + 1] + bv1;
                if (act) { v0 = fmaxf(v0, 0.f); v1 = fmaxf(v1, 0.f); }
                Out[(size_t)row * N + col]     = v0 * rm;
                Out[(size_t)row * N + col + 1] = v1 * rm;
            }
        }
    }
}

template<int MT, int K>
__global__ __launch_bounds__(256)
void pgemm_kernel(const float* __restrict__ Aext, int Aid,
                  const float* __restrict__ W, const float* __restrict__ bias,
                  int Oid, int N, int act, const float* __restrict__ rowmask)
{
    const float* A = Aext ? Aext : scratch_ptr(Aid);
    pgemm_core<MT, K>(A, W, bias, scratch_ptr(Oid), N, act, rowmask,
                      blockIdx.y * MT * 32, blockIdx.x * 64);
}

// fused Q/K/V projections (MT=2: 192 blocks)
__global__ __launch_bounds__(256)
void qkv_kernel(const float* __restrict__ X,
                const float* __restrict__ Wq, const float* __restrict__ bq,
                const float* __restrict__ Wk, const float* __restrict__ bk,
                const float* __restrict__ Wv, const float* __restrict__ bv,
                const float* __restrict__ rowmask)
{
    const float* W; const float* b; float* Out;
    if (blockIdx.z == 0)      { W = Wq; b = bq; Out = g_Q; }
    else if (blockIdx.z == 1) { W = Wk; b = bk; Out = g_K; }
    else                      { W = Wv; b = bv; Out = g_V; }
    pgemm_core<2, DXD>(X, W, b, Out, DXD, 0, rowmask,
                       blockIdx.y * 64, blockIdx.x * 64);
}

// ---------------- fused Wo-GEMM(+mask) + residual + LayerNorm ----------------
#define SA2 20
#define SB2 260

__global__ __launch_bounds__(256)
void gemm_ln_kernel(const float* __restrict__ W,
                    const float* __restrict__ bias,
                    const float* __restrict__ rowmask,
                    const float* __restrict__ R,
                    const float* __restrict__ g, const float* __restrict__ beta)
{
    constexpr int K = DXD;
    constexpr int NK = K / 16;
    const float* A = g_att;
    float* Out = g_X1;

    __shared__ __align__(16) float As[2][16][SA2];
    __shared__ __align__(16) float Bs[2][16][SB2];

    const int tid  = threadIdx.x;
    const int lane = tid & 31;
    const int wid  = tid >> 5;
    const int lr = lane >> 2;
    const int lc = lane & 3;
    const int row0 = blockIdx.x * 16;

    const int ar = tid >> 2, aq = tid & 3;
    const bool aon = (tid < 64);
    const int bq = tid & 63;
    const int br_[4] = { (tid + 0) >> 6, (tid + 256) >> 6, (tid + 512) >> 6, (tid + 768) >> 6 };

    unsigned sA[2], sB[2][4];
#pragma unroll
    for (int bf = 0; bf < 2; bf++) {
        sA[bf] = (unsigned)__cvta_generic_to_shared(&As[bf][ar & 15][aq * 4]);
#pragma unroll
        for (int it = 0; it < 4; it++)
            sB[bf][it] = (unsigned)__cvta_generic_to_shared(&Bs[bf][br_[it]][bq * 4]);
    }

    if (aon) cp_async16(sA[0], &A[(size_t)(row0 + ar) * K + aq * 4]);
#pragma unroll
    for (int it = 0; it < 4; it++)
        cp_async16(sB[0][it], &W[(size_t)br_[it] * DXD + bq * 4]);
    CP_COMMIT();

    float acc[4][4];
#pragma unroll
    for (int nt = 0; nt < 4; nt++)
#pragma unroll
        for (int i = 0; i < 4; i++) acc[nt][i] = 0.f;

    int buf = 0;
#pragma unroll 2
    for (int ki = 0; ki < NK; ki++) {
        if (ki + 1 < NK) {
            const int kt = (ki + 1) * 16;
            if (aon) cp_async16(sA[buf ^ 1], &A[(size_t)(row0 + ar) * K + kt + aq * 4]);
#pragma unroll
            for (int it = 0; it < 4; it++)
                cp_async16(sB[buf ^ 1][it], &W[(size_t)(kt + br_[it]) * DXD + bq * 4]);
            CP_COMMIT();
            CP_WAIT(1);
        } else {
            CP_WAIT(0);
        }
        __syncthreads();

#pragma unroll
        for (int ks = 0; ks < 2; ks++) {
            const int k0 = ks * 8;
            const float* pa = &As[buf][lr][k0 + lc];
            unsigned a0 = f2tf32_u(pa[0]);
            unsigned a1 = f2tf32_u(pa[8 * SA2]);
            unsigned a2 = f2tf32_u(pa[4]);
            unsigned a3 = f2tf32_u(pa[8 * SA2 + 4]);
#pragma unroll
            for (int nt = 0; nt < 4; nt++) {
                const float* pb = &Bs[buf][k0 + lc][wid * 32 + nt * 8 + lr];
                unsigned b0 = f2tf32_u(pb[0]);
                unsigned b1 = f2tf32_u(pb[4 * SB2]);
                mma_tf32(acc[nt][0], acc[nt][1], acc[nt][2], acc[nt][3],
                         a0, a1, a2, a3, b0, b1);
            }
        }
        __syncthreads();
        buf ^= 1;
    }

    float (*S)[SB2] = Bs[0];
#pragma unroll
    for (int nt = 0; nt < 4; nt++) {
        const int col = wid * 32 + nt * 8 + 2 * lc;
#pragma unroll
        for (int h = 0; h < 2; h++) {
            S[lr + 8 * h][col]     = acc[nt][2 * h + 0];
            S[lr + 8 * h][col + 1] = acc[nt][2 * h + 1];
        }
    }
    __syncthreads();

#pragma unroll
    for (int rr = 0; rr < 2; rr++) {
        const int r = wid * 2 + rr;
        const int grow = row0 + r;
        const float rm = rowmask[grow];
        const int c0 = lane * 8;

        float vals[8];
        float sum = 0.f, sumsq = 0.f;
#pragma unroll
        for (int i = 0; i < 8; i++) {
            const int c = c0 + i;
            const float v = (S[r][c] + bias[c]) * rm + R[(size_t)grow * DXD + c];
            vals[i] = v;
            sum += v;
            sumsq = fmaf(v, v, sumsq);
        }
#pragma unroll
        for (int o = 16; o; o >>= 1) {
            sum   += __shfl_xor_sync(0xffffffffu, sum,   o);
            sumsq += __shfl_xor_sync(0xffffffffu, sumsq, o);
        }
        const float mu  = sum * (1.f / DXD);
        const float var = sumsq * (1.f / DXD) - mu * mu;
        const float inv = rsqrtf(var + EPSV);

        float o8[8];
#pragma unroll
        for (int i = 0; i < 8; i++)
            o8[i] = (vals[i] - mu) * inv * g[c0 + i] + beta[c0 + i];

        *(float4*)&Out[(size_t)grow * DXD + c0]     = make_float4(o8[0], o8[1], o8[2], o8[3]);
        *(float4*)&Out[(size_t)grow * DXD + c0 + 4] = make_float4(o8[4], o8[5], o8[6], o8[7]);
    }
}

// ---------------- attention: 4-stage cp.async pipeline, 2 query rows / block ----------------
// Tiles of 4 j-rows; 4 smem buffers (64 KB) give 3-tile prefetch lookahead.
__global__ __launch_bounds__(256)
void attn_kernel(const float* __restrict__ e_add,
                 const float* __restrict__ e_mul,
                 const float* __restrict__ y_x_add,
                 const float* __restrict__ y_x_mul,
                 const float* __restrict__ node_mask)
{
    const int bp = blockIdx.x;            // 0..511
    const int b  = bp >> 7;
    const int i0 = (bp & 127) * 2;
    const int bi0 = b * NN + i0;
    const int d = threadIdx.x;

    __shared__ float s_ee[2][NN];
    __shared__ float s_on[NN];
    __shared__ __align__(16) float s_em[4][2][4][NN];   // [buf][row][jj][d] 32KB
    __shared__ __align__(16) float s_ea[4][2][4][NN];   // 32KB

    {
        const float mj  = node_mask[b * NN + d];
        const float mi0 = node_mask[b * NN + i0];
        const float mi1 = node_mask[b * NN + i0 + 1];
        s_on[d]    = (mj > 0.f) ? 1.f : 0.f;
        s_ee[0][d] = mi0 * mj;
        s_ee[1][d] = mi1 * mj;
    }
    __syncthreads();

    const float inv_sqrt_df = 0.1767766952966369f;
    const float q0 = g_Q[(size_t)bi0 * DXD + d] * inv_sqrt_df;
    const float q1 = g_Q[(size_t)(bi0 + 1) * DXD + d] * inv_sqrt_df;

    // chunk decode: 1024 16B-chunks per tile (2 arrays x 2 rows x 4 j x 64 segs)
    const float* gsrc[4];
    unsigned sdb[4];                       // smem base (buffer 0); buffer stride = 8192B
    const unsigned BUFSTRIDE = 2 * 4 * NN * 4;   // 8192 bytes
#pragma unroll
    for (int c = 0; c < 4; c++) {
        const int id  = d + c * 256;
        const int arr = id >> 9;
        const int r   = (id >> 8) & 1;
        const int jj  = (id >> 6) & 3;
        const int seg = id & 63;
        const float* base = arr ? e_add : e_mul;
        gsrc[c] = base + ((size_t)(bi0 + r) * NN + jj) * DXD + seg * 4;
        float* sp = arr ? &s_ea[0][r][jj][seg * 4] : &s_em[0][r][jj][seg * 4];
        sdb[c] = (unsigned)__cvta_generic_to_shared(sp);
    }

    // prologue: issue tiles 0,1,2
#pragma unroll
    for (int tt = 0; tt < 3; tt++) {
#pragma unroll
        for (int c = 0; c < 4; c++)
            cp_async16(sdb[c] + tt * BUFSTRIDE, gsrc[c] + (size_t)tt * (4 * DXD));
        CP_COMMIT();
    }

    const float* __restrict__ pk = g_K + (size_t)b * NN * DXD + d;
    const float* __restrict__ pv = g_V + (size_t)b * NN * DXD + d;

    float s0 = 0.f, a0 = 0.f, s1 = 0.f, a1 = 0.f;

    int buf = 0;
    for (int t = 0; t < 64; t++) {
        if (t < 62)      CP_WAIT(2);
        else if (t == 62) CP_WAIT(1);
        else              CP_WAIT(0);
        __syncthreads();

        const int j0 = t * 4;
#pragma unroll
        for (int jj = 0; jj < 4; jj++) {
            const int j = j0 + jj;
            const float kk = pk[(size_t)j * DXD];
            const float vv = pv[(size_t)j * DXD];
            const float on  = s_on[j];
            const float ee0 = s_ee[0][j];
            const float ee1 = s_ee[1][j];
            const float em0 = s_em[buf][0][jj][d];
            const float ea0 = s_ea[buf][0][jj][d];
            const float em1 = s_em[buf][1][jj][d];
            const float ea1 = s_ea[buf][1][jj][d];

            float y0 = fmaf(q0 * kk, fmaf(em0, ee0, 1.f), ea0 * ee0);
            float p0 = on * __expf(y0);
            s0 += p0;  a0 = fmaf(p0, vv, a0);

            float y1 = fmaf(q1 * kk, fmaf(em1, ee1, 1.f), ea1 * ee1);
            float p1 = on * __expf(y1);
            s1 += p1;  a1 = fmaf(p1, vv, a1);
        }

        // issue tile t+3 into buffer (buf+3)&3 == (t-1)&3 — its readers all
        // passed this iteration's barrier already.
        if (t + 3 < 64) {
            const int nb = (buf + 3) & 3;
            const size_t off = (size_t)(t + 3) * (4 * DXD);
#pragma unroll
            for (int c = 0; c < 4; c++)
                cp_async16(sdb[c] + nb * BUFSTRIDE, gsrc[c] + off);
            CP_COMMIT();
        }
        buf = (buf + 1) & 3;
    }

    const float ya = y_x_add[b * DXD + d];
    const float ym = y_x_mul[b * DXD + d] + 1.f;
    g_att[(size_t)bi0 * DXD + d]       = ya + ym * (a0 / s0);
    g_att[(size_t)(bi0 + 1) * DXD + d] = ya + ym * (a1 / s1);
}

// ---------------- single-pass layer norm over last dim (256) ----------------
__global__ __launch_bounds__(256)
void ln_kernel(int Aid, int Bid,
               const float* __restrict__ g, const float* __restrict__ beta,
               float* __restrict__ Out)
{
    const float* A = scratch_ptr(Aid);
    const float* B = scratch_ptr(Bid);

    __shared__ float red[16];

    const int row = blockIdx.x;
    const int t   = threadIdx.x;

    const float x = A[(size_t)row * DXD + t] + B[(size_t)row * DXD + t];
    float sx = x, sxx = x * x;
#pragma unroll
    for (int o = 16; o; o >>= 1) {
        sx  += __shfl_xor_sync(0xffffffffu, sx,  o);
        sxx += __shfl_xor_sync(0xffffffffu, sxx, o);
    }
    if ((t & 31) == 0) { red[t >> 5] = sx; red[8 + (t >> 5)] = sxx; }
    __syncthreads();
    sx  = red[0] + red[1] + red[2]  + red[3]  + red[4]  + red[5]  + red[6]  + red[7];
    sxx = red[8] + red[9] + red[10] + red[11] + red[12] + red[13] + red[14] + red[15];

    const float mu  = sx * (1.f / DXD);
    const float var = sxx * (1.f / DXD) - mu * mu;
    Out[(size_t)row * DXD + t] = (x - mu) * rsqrtf(var + EPSV) * g[t] + beta[t];
}

// ---------------- launch ----------------
extern "C" void kernel_launch(void* const* d_in, const int* in_sizes, int n_in,
                              void* d_out, int out_size)
{
    const float* X      = (const float*)d_in[0];
    const float* e_add  = (const float*)d_in[1];
    const float* e_mul  = (const float*)d_in[2];
    const float* yxa    = (const float*)d_in[3];
    const float* yxm    = (const float*)d_in[4];
    const float* nmask  = (const float*)d_in[5];
    const float* Wq     = (const float*)d_in[6];
    const float* bq     = (const float*)d_in[7];
    const float* Wk     = (const float*)d_in[8];
    const float* bk     = (const float*)d_in[9];
    const float* Wv     = (const float*)d_in[10];
    const float* bv     = (const float*)d_in[11];
    const float* Wo     = (const float*)d_in[12];
    const float* bo     = (const float*)d_in[13];
    const float* W1     = (const float*)d_in[14];
    const float* b1     = (const float*)d_in[15];
    const float* W2     = (const float*)d_in[16];
    const float* b2     = (const float*)d_in[17];
    const float* g1     = (const float*)d_in[18];
    const float* beta1  = (const float*)d_in[19];
    const float* g2     = (const float*)d_in[20];
    const float* b2ln   = (const float*)d_in[21];
    float* out          = (float*)d_out;

    // 1) fused QKV: MT=2 -> 192 blocks
    qkv_kernel<<<dim3(DXD / 64, MROWS / 64, 3), 256>>>(X, Wq, bq, Wk, bk, Wv, bv, nmask);

    // 2) attention (4-stage cp.async, 2 rows/block): 512 blocks
    attn_kernel<<<MROWS / 2, 256>>>(e_add, e_mul, yxa, yxm, nmask);

    // 3) fused: X1 = LN(X + mask*(att @ Wo + bo)). 64 blocks.
    gemm_ln_kernel<<<MROWS / 16, 256>>>(Wo, bo, nmask, X, g1, beta1);

    // 4) FFN1: relu(X1 @ W1 + b1): MT=2 -> 256 blocks
    pgemm_kernel<2, DXD><<<dim3(DFFD / 64, MROWS / 64), 256>>>(nullptr, 5, W1, b1, 6, DFFD, 1, nullptr);

    // 5) FFN2: ffn1 @ W2 + b2: 128 blocks, K=1024
    pgemm_kernel<1, DFFD><<<dim3(DXD / 64, MROWS / 32), 256>>>(nullptr, 6, W2, b2, 7, DXD, 0, nullptr);

    // 6) LN2 -> out
    ln_kernel<<<MROWS, 256>>>(5, 7, g2, b2ln, out);
}

// round 12
// speedup vs baseline: 1.2356x; 1.2356x over previous
#include <cuda_runtime.h>
#include <math.h>

#define BSZ 4
#define NN 256
#define DXD 256
#define DFFD 1024
#define EPSV 1e-5f
#define MROWS (BSZ*NN)   // 1024

// ---------------- scratch (allocation-free) ----------------
__device__ __align__(16) float g_Q   [MROWS*DXD];
__device__ __align__(16) float g_K   [MROWS*DXD];
__device__ __align__(16) float g_V   [MROWS*DXD];
__device__ __align__(16) float g_att [MROWS*DXD];
__device__ __align__(16) float g_X1  [MROWS*DXD];
__device__ __align__(16) float g_ffn1[MROWS*DFFD];
__device__ __align__(16) float g_ffn2[MROWS*DXD];

__device__ __forceinline__ float* scratch_ptr(int id) {
    switch (id) {
        case 0: return g_Q;
        case 1: return g_K;
        case 2: return g_V;
        case 3: return g_att;
        case 5: return g_X1;
        case 6: return g_ffn1;
        default: return g_ffn2;
    }
}

// ---------------- tf32 / cp.async helpers ----------------
__device__ __forceinline__ unsigned f2tf32_u(float x) {
    unsigned r;
    asm("cvt.rna.tf32.f32 %0, %1;" : "=r"(r) : "f"(x));
    return r;
}

__device__ __forceinline__ void cp_async16(unsigned saddr, const void* gptr) {
    asm volatile("cp.async.ca.shared.global [%0], [%1], 16;" :: "r"(saddr), "l"(gptr));
}
#define CP_COMMIT() asm volatile("cp.async.commit_group;" ::: "memory")
#define CP_WAIT(n)  asm volatile("cp.async.wait_group %0;" :: "n"(n) : "memory")

__device__ __forceinline__ void mma_tf32(float& c0, float& c1, float& c2, float& c3,
                                         unsigned a0, unsigned a1, unsigned a2, unsigned a3,
                                         unsigned b0, unsigned b1)
{
    asm volatile(
        "mma.sync.aligned.m16n8k8.row.col.f32.tf32.tf32.f32 "
        "{%0,%1,%2,%3}, {%4,%5,%6,%7}, {%8,%9}, {%0,%1,%2,%3};"
        : "+f"(c0), "+f"(c1), "+f"(c2), "+f"(c3)
        : "r"(a0), "r"(a1), "r"(a2), "r"(a3), "r"(b0), "r"(b1));
}

// ---------------- tf32 GEMM, cp.async double-buffered, cvt at fragment load ----------------
#define SA 36
#define SB 68

template<int MT, int K>
__device__ __forceinline__ void pgemm_core(const float* __restrict__ A,
                                           const float* __restrict__ W,
                                           const float* __restrict__ bias,
                                           float* __restrict__ Out,
                                           int N, int act,
                                           const float* __restrict__ rowmask,
                                           int row0, int col0)
{
    constexpr int BM  = MT * 32;
    constexpr int AIT = BM / 32;
    constexpr int NK  = K / 32;

    __shared__ __align__(16) float As[2][BM][SA];
    __shared__ __align__(16) float Bs[2][32][SB];

    const int tid    = threadIdx.x;
    const int lane   = tid & 31;
    const int wid    = tid >> 5;
    const int warp_m = wid & 1;
    const int warp_n = wid >> 1;
    const int lr = lane >> 2;
    const int lc = lane & 3;

    int am_[AIT];
#pragma unroll
    for (int it = 0; it < AIT; it++) am_[it] = (tid + it * 256) >> 3;
    const int aq  = tid & 7;
    const int bk_[2] = { (tid + 0) >> 4, (tid + 256) >> 4 };
    const int bq  = tid & 15;

    unsigned sA[2][AIT], sB[2][2];
#pragma unroll
    for (int bf = 0; bf < 2; bf++) {
#pragma unroll
        for (int it = 0; it < AIT; it++)
            sA[bf][it] = (unsigned)__cvta_generic_to_shared(&As[bf][am_[it]][aq * 4]);
#pragma unroll
        for (int it = 0; it < 2; it++)
            sB[bf][it] = (unsigned)__cvta_generic_to_shared(&Bs[bf][bk_[it]][bq * 4]);
    }

#pragma unroll
    for (int it = 0; it < AIT; it++)
        cp_async16(sA[0][it], &A[(size_t)(row0 + am_[it]) * K + aq * 4]);
#pragma unroll
    for (int it = 0; it < 2; it++)
        cp_async16(sB[0][it], &W[(size_t)bk_[it] * N + col0 + bq * 4]);
    CP_COMMIT();

    float acc[MT][2][4];
#pragma unroll
    for (int mt = 0; mt < MT; mt++)
#pragma unroll
        for (int nt = 0; nt < 2; nt++)
#pragma unroll
            for (int i = 0; i < 4; i++) acc[mt][nt][i] = 0.f;

    int buf = 0;
#pragma unroll 2
    for (int ki = 0; ki < NK; ki++) {
        if (ki + 1 < NK) {
            const int kt = (ki + 1) * 32;
#pragma unroll
            for (int it = 0; it < AIT; it++)
                cp_async16(sA[buf ^ 1][it], &A[(size_t)(row0 + am_[it]) * K + kt + aq * 4]);
#pragma unroll
            for (int it = 0; it < 2; it++)
                cp_async16(sB[buf ^ 1][it], &W[(size_t)(kt + bk_[it]) * N + col0 + bq * 4]);
            CP_COMMIT();
            CP_WAIT(1);
        } else {
            CP_WAIT(0);
        }
        __syncthreads();

#pragma unroll
        for (int ks = 0; ks < 4; ks++) {
            const int k0 = ks * 8;
            unsigned b0[2], b1[2];
#pragma unroll
            for (int nt = 0; nt < 2; nt++) {
                const float* pb = &Bs[buf][k0 + lc][warp_n * 16 + nt * 8 + lr];
                b0[nt] = f2tf32_u(pb[0]);
                b1[nt] = f2tf32_u(pb[4 * SB]);
            }
#pragma unroll
            for (int mt = 0; mt < MT; mt++) {
                const float* pa = &As[buf][warp_m * (BM / 2) + mt * 16 + lr][k0 + lc];
                unsigned a0 = f2tf32_u(pa[0]);
                unsigned a1 = f2tf32_u(pa[8 * SA]);
                unsigned a2 = f2tf32_u(pa[4]);
                unsigned a3 = f2tf32_u(pa[8 * SA + 4]);
#pragma unroll
                for (int nt = 0; nt < 2; nt++)
                    mma_tf32(acc[mt][nt][0], acc[mt][nt][1], acc[mt][nt][2], acc[mt][nt][3],
                             a0, a1, a2, a3, b0[nt], b1[nt]);
            }
        }
        __syncthreads();
        buf ^= 1;
    }

#pragma unroll
    for (int mt = 0; mt < MT; mt++) {
#pragma unroll
        for (int nt = 0; nt < 2; nt++) {
            const int col = col0 + warp_n * 16 + nt * 8 + 2 * lc;
            const float bv0 = bias[col], bv1 = bias[col + 1];
#pragma unroll
            for (int h = 0; h < 2; h++) {
                const int row = row0 + warp_m * (BM / 2) + mt * 16 + lr + h * 8;
                const float rm = rowmask ? rowmask[row] : 1.f;
                float v0 = acc[mt][nt][2 * h + 0] + bv0;
                float v1 = acc[mt][nt][2 * h + 1] + bv1;
                if (act) { v0 = fmaxf(v0, 0.f); v1 = fmaxf(v1, 0.f); }
                Out[(size_t)row * N + col]     = v0 * rm;
                Out[(size_t)row * N + col + 1] = v1 * rm;
            }
        }
    }
}

template<int MT, int K>
__global__ __launch_bounds__(256)
void pgemm_kernel(const float* __restrict__ Aext, int Aid,
                  const float* __restrict__ W, const float* __restrict__ bias,
                  int Oid, int N, int act, const float* __restrict__ rowmask)
{
    const float* A = Aext ? Aext : scratch_ptr(Aid);
    pgemm_core<MT, K>(A, W, bias, scratch_ptr(Oid), N, act, rowmask,
                      blockIdx.y * MT * 32, blockIdx.x * 64);
}

// fused Q/K/V projections (MT=2: 192 blocks)
__global__ __launch_bounds__(256)
void qkv_kernel(const float* __restrict__ X,
                const float* __restrict__ Wq, const float* __restrict__ bq,
                const float* __restrict__ Wk, const float* __restrict__ bk,
                const float* __restrict__ Wv, const float* __restrict__ bv,
                const float* __restrict__ rowmask)
{
    const float* W; const float* b; float* Out;
    if (blockIdx.z == 0)      { W = Wq; b = bq; Out = g_Q; }
    else if (blockIdx.z == 1) { W = Wk; b = bk; Out = g_K; }
    else                      { W = Wv; b = bv; Out = g_V; }
    pgemm_core<2, DXD>(X, W, b, Out, DXD, 0, rowmask,
                       blockIdx.y * 64, blockIdx.x * 64);
}

// ---------------- fused Wo-GEMM(+mask) + residual + LayerNorm ----------------
#define SA2 20
#define SB2 260

__global__ __launch_bounds__(256)
void gemm_ln_kernel(const float* __restrict__ W,
                    const float* __restrict__ bias,
                    const float* __restrict__ rowmask,
                    const float* __restrict__ R,
                    const float* __restrict__ g, const float* __restrict__ beta)
{
    constexpr int K = DXD;
    constexpr int NK = K / 16;
    const float* A = g_att;
    float* Out = g_X1;

    __shared__ __align__(16) float As[2][16][SA2];
    __shared__ __align__(16) float Bs[2][16][SB2];

    const int tid  = threadIdx.x;
    const int lane = tid & 31;
    const int wid  = tid >> 5;
    const int lr = lane >> 2;
    const int lc = lane & 3;
    const int row0 = blockIdx.x * 16;

    const int ar = tid >> 2, aq = tid & 3;
    const bool aon = (tid < 64);
    const int bq = tid & 63;
    const int br_[4] = { (tid + 0) >> 6, (tid + 256) >> 6, (tid + 512) >> 6, (tid + 768) >> 6 };

    unsigned sA[2], sB[2][4];
#pragma unroll
    for (int bf = 0; bf < 2; bf++) {
        sA[bf] = (unsigned)__cvta_generic_to_shared(&As[bf][ar & 15][aq * 4]);
#pragma unroll
        for (int it = 0; it < 4; it++)
            sB[bf][it] = (unsigned)__cvta_generic_to_shared(&Bs[bf][br_[it]][bq * 4]);
    }

    if (aon) cp_async16(sA[0], &A[(size_t)(row0 + ar) * K + aq * 4]);
#pragma unroll
    for (int it = 0; it < 4; it++)
        cp_async16(sB[0][it], &W[(size_t)br_[it] * DXD + bq * 4]);
    CP_COMMIT();

    float acc[4][4];
#pragma unroll
    for (int nt = 0; nt < 4; nt++)
#pragma unroll
        for (int i = 0; i < 4; i++) acc[nt][i] = 0.f;

    int buf = 0;
#pragma unroll 2
    for (int ki = 0; ki < NK; ki++) {
        if (ki + 1 < NK) {
            const int kt = (ki + 1) * 16;
            if (aon) cp_async16(sA[buf ^ 1], &A[(size_t)(row0 + ar) * K + kt + aq * 4]);
#pragma unroll
            for (int it = 0; it < 4; it++)
                cp_async16(sB[buf ^ 1][it], &W[(size_t)(kt + br_[it]) * DXD + bq * 4]);
            CP_COMMIT();
            CP_WAIT(1);
        } else {
            CP_WAIT(0);
        }
        __syncthreads();

#pragma unroll
        for (int ks = 0; ks < 2; ks++) {
            const int k0 = ks * 8;
            const float* pa = &As[buf][lr][k0 + lc];
            unsigned a0 = f2tf32_u(pa[0]);
            unsigned a1 = f2tf32_u(pa[8 * SA2]);
            unsigned a2 = f2tf32_u(pa[4]);
            unsigned a3 = f2tf32_u(pa[8 * SA2 + 4]);
#pragma unroll
            for (int nt = 0; nt < 4; nt++) {
                const float* pb = &Bs[buf][k0 + lc][wid * 32 + nt * 8 + lr];
                unsigned b0 = f2tf32_u(pb[0]);
                unsigned b1 = f2tf32_u(pb[4 * SB2]);
                mma_tf32(acc[nt][0], acc[nt][1], acc[nt][2], acc[nt][3],
                         a0, a1, a2, a3, b0, b1);
            }
        }
        __syncthreads();
        buf ^= 1;
    }

    float (*S)[SB2] = Bs[0];
#pragma unroll
    for (int nt = 0; nt < 4; nt++) {
        const int col = wid * 32 + nt * 8 + 2 * lc;
#pragma unroll
        for (int h = 0; h < 2; h++) {
            S[lr + 8 * h][col]     = acc[nt][2 * h + 0];
            S[lr + 8 * h][col + 1] = acc[nt][2 * h + 1];
        }
    }
    __syncthreads();

#pragma unroll
    for (int rr = 0; rr < 2; rr++) {
        const int r = wid * 2 + rr;
        const int grow = row0 + r;
        const float rm = rowmask[grow];
        const int c0 = lane * 8;

        float vals[8];
        float sum = 0.f, sumsq = 0.f;
#pragma unroll
        for (int i = 0; i < 8; i++) {
            const int c = c0 + i;
            const float v = (S[r][c] + bias[c]) * rm + R[(size_t)grow * DXD + c];
            vals[i] = v;
            sum += v;
            sumsq = fmaf(v, v, sumsq);
        }
#pragma unroll
        for (int o = 16; o; o >>= 1) {
            sum   += __shfl_xor_sync(0xffffffffu, sum,   o);
            sumsq += __shfl_xor_sync(0xffffffffu, sumsq, o);
        }
        const float mu  = sum * (1.f / DXD);
        const float var = sumsq * (1.f / DXD) - mu * mu;
        const float inv = rsqrtf(var + EPSV);

        float o8[8];
#pragma unroll
        for (int i = 0; i < 8; i++)
            o8[i] = (vals[i] - mu) * inv * g[c0 + i] + beta[c0 + i];

        *(float4*)&Out[(size_t)grow * DXD + c0]     = make_float4(o8[0], o8[1], o8[2], o8[3]);
        *(float4*)&Out[(size_t)grow * DXD + c0 + 4] = make_float4(o8[4], o8[5], o8[6], o8[7]);
    }
}

// ---------------- attention: 2-stage cp.async, 2 query rows / block (R10 best) ----------------
__global__ __launch_bounds__(256)
void attn_kernel(const float* __restrict__ e_add,
                 const float* __restrict__ e_mul,
                 const float* __restrict__ y_x_add,
                 const float* __restrict__ y_x_mul,
                 const float* __restrict__ node_mask)
{
    const int bp = blockIdx.x;            // 0..511
    const int b  = bp >> 7;
    const int i0 = (bp & 127) * 2;
    const int bi0 = b * NN + i0;
    const int d = threadIdx.x;

    __shared__ float s_ee[2][NN];
    __shared__ float s_on[NN];
    __shared__ __align__(16) float s_em[2][2][4][NN];   // [buf][row][jj][d] 16KB
    __shared__ __align__(16) float s_ea[2][2][4][NN];   // 16KB

    {
        const float mj  = node_mask[b * NN + d];
        const float mi0 = node_mask[b * NN + i0];
        const float mi1 = node_mask[b * NN + i0 + 1];
        s_on[d]    = (mj > 0.f) ? 1.f : 0.f;
        s_ee[0][d] = mi0 * mj;
        s_ee[1][d] = mi1 * mj;
    }
    __syncthreads();

    const float inv_sqrt_df = 0.1767766952966369f;
    const float q0 = g_Q[(size_t)bi0 * DXD + d] * inv_sqrt_df;
    const float q1 = g_Q[(size_t)(bi0 + 1) * DXD + d] * inv_sqrt_df;

    // chunk decode: 1024 16B-chunks per tile (2 arrays x 2 rows x 4 j x 64 segs)
    const float* gsrc[4];
    unsigned sd0[4], sd1[4];
#pragma unroll
    for (int c = 0; c < 4; c++) {
        const int id  = d + c * 256;
        const int arr = id >> 9;
        const int r   = (id >> 8) & 1;
        const int jj  = (id >> 6) & 3;
        const int seg = id & 63;
        const float* base = arr ? e_add : e_mul;
        gsrc[c] = base + ((size_t)(bi0 + r) * NN + jj) * DXD + seg * 4;
        float* s0p = arr ? &s_ea[0][r][jj][seg * 4] : &s_em[0][r][jj][seg * 4];
        float* s1p = arr ? &s_ea[1][r][jj][seg * 4] : &s_em[1][r][jj][seg * 4];
        sd0[c] = (unsigned)__cvta_generic_to_shared(s0p);
        sd1[c] = (unsigned)__cvta_generic_to_shared(s1p);
    }

#pragma unroll
    for (int c = 0; c < 4; c++) cp_async16(sd0[c], gsrc[c]);
    CP_COMMIT();

    const float* __restrict__ pk = g_K + (size_t)b * NN * DXD + d;
    const float* __restrict__ pv = g_V + (size_t)b * NN * DXD + d;

    float s0 = 0.f, a0 = 0.f, s1 = 0.f, a1 = 0.f;

    int buf = 0;
    for (int t = 0; t < 64; t++) {
        if (t < 63) {
            const size_t off = (size_t)(t + 1) * (4 * DXD);
#pragma unroll
            for (int c = 0; c < 4; c++)
                cp_async16(buf ? sd0[c] : sd1[c], gsrc[c] + off);
            CP_COMMIT();
            CP_WAIT(1);
        } else {
            CP_WAIT(0);
        }
        __syncthreads();

        const int j0 = t * 4;
#pragma unroll
        for (int jj = 0; jj < 4; jj++) {
            const int j = j0 + jj;
            const float kk = pk[(size_t)j * DXD];
            const float vv = pv[(size_t)j * DXD];
            const float on  = s_on[j];
            const float ee0 = s_ee[0][j];
            const float ee1 = s_ee[1][j];
            const float em0 = s_em[buf][0][jj][d];
            const float ea0 = s_ea[buf][0][jj][d];
            const float em1 = s_em[buf][1][jj][d];
            const float ea1 = s_ea[buf][1][jj][d];

            float y0 = fmaf(q0 * kk, fmaf(em0, ee0, 1.f), ea0 * ee0);
            float p0 = on * __expf(y0);
            s0 += p0;  a0 = fmaf(p0, vv, a0);

            float y1 = fmaf(q1 * kk, fmaf(em1, ee1, 1.f), ea1 * ee1);
            float p1 = on * __expf(y1);
            s1 += p1;  a1 = fmaf(p1, vv, a1);
        }
        __syncthreads();
        buf ^= 1;
    }

    const float ya = y_x_add[b * DXD + d];
    const float ym = y_x_mul[b * DXD + d] + 1.f;
    g_att[(size_t)bi0 * DXD + d]       = ya + ym * (a0 / s0);
    g_att[(size_t)(bi0 + 1) * DXD + d] = ya + ym * (a1 / s1);
}

// ---------------- single-pass layer norm over last dim (256) ----------------
__global__ __launch_bounds__(256)
void ln_kernel(int Aid, int Bid,
               const float* __restrict__ g, const float* __restrict__ beta,
               float* __restrict__ Out)
{
    const float* A = scratch_ptr(Aid);
    const float* B = scratch_ptr(Bid);

    __shared__ float red[16];

    const int row = blockIdx.x;
    const int t   = threadIdx.x;

    const float x = A[(size_t)row * DXD + t] + B[(size_t)row * DXD + t];
    float sx = x, sxx = x * x;
#pragma unroll
    for (int o = 16; o; o >>= 1) {
        sx  += __shfl_xor_sync(0xffffffffu, sx,  o);
        sxx += __shfl_xor_sync(0xffffffffu, sxx, o);
    }
    if ((t & 31) == 0) { red[t >> 5] = sx; red[8 + (t >> 5)] = sxx; }
    __syncthreads();
    sx  = red[0] + red[1] + red[2]  + red[3]  + red[4]  + red[5]  + red[6]  + red[7];
    sxx = red[8] + red[9] + red[10] + red[11] + red[12] + red[13] + red[14] + red[15];

    const float mu  = sx * (1.f / DXD);
    const float var = sxx * (1.f / DXD) - mu * mu;
    Out[(size_t)row * DXD + t] = (x - mu) * rsqrtf(var + EPSV) * g[t] + beta[t];
}

// ---------------- launch ----------------
extern "C" void kernel_launch(void* const* d_in, const int* in_sizes, int n_in,
                              void* d_out, int out_size)
{
    const float* X      = (const float*)d_in[0];
    const float* e_add  = (const float*)d_in[1];
    const float* e_mul  = (const float*)d_in[2];
    const float* yxa    = (const float*)d_in[3];
    const float* yxm    = (const float*)d_in[4];
    const float* nmask  = (const float*)d_in[5];
    const float* Wq     = (const float*)d_in[6];
    const float* bq     = (const float*)d_in[7];
    const float* Wk     = (const float*)d_in[8];
    const float* bk     = (const float*)d_in[9];
    const float* Wv     = (const float*)d_in[10];
    const float* bv     = (const float*)d_in[11];
    const float* Wo     = (const float*)d_in[12];
    const float* bo     = (const float*)d_in[13];
    const float* W1     = (const float*)d_in[14];
    const float* b1     = (const float*)d_in[15];
    const float* W2     = (const float*)d_in[16];
    const float* b2     = (const float*)d_in[17];
    const float* g1     = (const float*)d_in[18];
    const float* beta1  = (const float*)d_in[19];
    const float* g2     = (const float*)d_in[20];
    const float* b2ln   = (const float*)d_in[21];
    float* out          = (float*)d_out;

    // 1) fused QKV: MT=2 -> 192 blocks
    qkv_kernel<<<dim3(DXD / 64, MROWS / 64, 3), 256>>>(X, Wq, bq, Wk, bk, Wv, bv, nmask);

    // 2) attention (2-stage cp.async, 2 rows/block): 512 blocks
    attn_kernel<<<MROWS / 2, 256>>>(e_add, e_mul, yxa, yxm, nmask);

    // 3) fused: X1 = LN(X + mask*(att @ Wo + bo)). 64 blocks.
    gemm_ln_kernel<<<MROWS / 16, 256>>>(Wo, bo, nmask, X, g1, beta1);

    // 4) FFN1: relu(X1 @ W1 + b1): MT=2 -> 256 blocks
    pgemm_kernel<2, DXD><<<dim3(DFFD / 64, MROWS / 64), 256>>>(nullptr, 5, W1, b1, 6, DFFD, 1, nullptr);

    // 5) FFN2: ffn1 @ W2 + b2: 128 blocks, K=1024
    pgemm_kernel<1, DFFD><<<dim3(DXD / 64, MROWS / 32), 256>>>(nullptr, 6, W2, b2, 7, DXD, 0, nullptr);

    // 6) LN2 -> out
    ln_kernel<<<MROWS, 256>>>(5, 7, g2, b2ln, out);
}

// round 13
// speedup vs baseline: 1.2865x; 1.0412x over previous
#include <cuda_runtime.h>
#include <math.h>

#define BSZ 4
#define NN 256
#define DXD 256
#define DFFD 1024
#define EPSV 1e-5f
#define MROWS (BSZ*NN)   // 1024

// ---------------- scratch (allocation-free) ----------------
__device__ __align__(16) float g_Q   [MROWS*DXD];
__device__ __align__(16) float g_K   [MROWS*DXD];
__device__ __align__(16) float g_V   [MROWS*DXD];
__device__ __align__(16) float g_att [MROWS*DXD];
__device__ __align__(16) float g_X1  [MROWS*DXD];
__device__ __align__(16) float g_ffn1[MROWS*DFFD];
__device__ __align__(16) float g_ffn2[MROWS*DXD];

__device__ __forceinline__ float* scratch_ptr(int id) {
    switch (id) {
        case 0: return g_Q;
        case 1: return g_K;
        case 2: return g_V;
        case 3: return g_att;
        case 5: return g_X1;
        case 6: return g_ffn1;
        default: return g_ffn2;
    }
}

// ---------------- cp.async helpers ----------------
__device__ __forceinline__ void cp_async16(unsigned saddr, const void* gptr) {
    asm volatile("cp.async.ca.shared.global [%0], [%1], 16;" :: "r"(saddr), "l"(gptr));
}
#define CP_COMMIT() asm volatile("cp.async.commit_group;" ::: "memory")
#define CP_WAIT(n)  asm volatile("cp.async.wait_group %0;" :: "n"(n) : "memory")

// HMMA.TF32 reads operand regs as tf32 (bits [31:13]); feeding raw fp32 bits
// gives truncation instead of round-to-nearest — error still within tf32 ulp.
__device__ __forceinline__ void mma_tf32(float& c0, float& c1, float& c2, float& c3,
                                         unsigned a0, unsigned a1, unsigned a2, unsigned a3,
                                         unsigned b0, unsigned b1)
{
    asm volatile(
        "mma.sync.aligned.m16n8k8.row.col.f32.tf32.tf32.f32 "
        "{%0,%1,%2,%3}, {%4,%5,%6,%7}, {%8,%9}, {%0,%1,%2,%3};"
        : "+f"(c0), "+f"(c1), "+f"(c2), "+f"(c3)
        : "r"(a0), "r"(a1), "r"(a2), "r"(a3), "r"(b0), "r"(b1));
}

// ---------------- tf32 GEMM, cp.async double-buffered, raw-bits fragments ----------------
#define SA 36
#define SB 68

template<int MT, int K>
__device__ __forceinline__ void pgemm_core(const float* __restrict__ A,
                                           const float* __restrict__ W,
                                           const float* __restrict__ bias,
                                           float* __restrict__ Out,
                                           int N, int act,
                                           const float* __restrict__ rowmask,
                                           int row0, int col0)
{
    constexpr int BM  = MT * 32;
    constexpr int AIT = BM / 32;
    constexpr int NK  = K / 32;

    __shared__ __align__(16) float As[2][BM][SA];
    __shared__ __align__(16) float Bs[2][32][SB];

    const int tid    = threadIdx.x;
    const int lane   = tid & 31;
    const int wid    = tid >> 5;
    const int warp_m = wid & 1;
    const int warp_n = wid >> 1;
    const int lr = lane >> 2;
    const int lc = lane & 3;

    int am_[AIT];
#pragma unroll
    for (int it = 0; it < AIT; it++) am_[it] = (tid + it * 256) >> 3;
    const int aq  = tid & 7;
    const int bk_[2] = { (tid + 0) >> 4, (tid + 256) >> 4 };
    const int bq  = tid & 15;

    unsigned sA[2][AIT], sB[2][2];
#pragma unroll
    for (int bf = 0; bf < 2; bf++) {
#pragma unroll
        for (int it = 0; it < AIT; it++)
            sA[bf][it] = (unsigned)__cvta_generic_to_shared(&As[bf][am_[it]][aq * 4]);
#pragma unroll
        for (int it = 0; it < 2; it++)
            sB[bf][it] = (unsigned)__cvta_generic_to_shared(&Bs[bf][bk_[it]][bq * 4]);
    }

#pragma unroll
    for (int it = 0; it < AIT; it++)
        cp_async16(sA[0][it], &A[(size_t)(row0 + am_[it]) * K + aq * 4]);
#pragma unroll
    for (int it = 0; it < 2; it++)
        cp_async16(sB[0][it], &W[(size_t)bk_[it] * N + col0 + bq * 4]);
    CP_COMMIT();

    float acc[MT][2][4];
#pragma unroll
    for (int mt = 0; mt < MT; mt++)
#pragma unroll
        for (int nt = 0; nt < 2; nt++)
#pragma unroll
            for (int i = 0; i < 4; i++) acc[mt][nt][i] = 0.f;

    int buf = 0;
#pragma unroll 2
    for (int ki = 0; ki < NK; ki++) {
        if (ki + 1 < NK) {
            const int kt = (ki + 1) * 32;
#pragma unroll
            for (int it = 0; it < AIT; it++)
                cp_async16(sA[buf ^ 1][it], &A[(size_t)(row0 + am_[it]) * K + kt + aq * 4]);
#pragma unroll
            for (int it = 0; it < 2; it++)
                cp_async16(sB[buf ^ 1][it], &W[(size_t)(kt + bk_[it]) * N + col0 + bq * 4]);
            CP_COMMIT();
            CP_WAIT(1);
        } else {
            CP_WAIT(0);
        }
        __syncthreads();

#pragma unroll
        for (int ks = 0; ks < 4; ks++) {
            const int k0 = ks * 8;
            unsigned b0[2], b1[2];
#pragma unroll
            for (int nt = 0; nt < 2; nt++) {
                const float* pb = &Bs[buf][k0 + lc][warp_n * 16 + nt * 8 + lr];
                b0[nt] = __float_as_uint(pb[0]);
                b1[nt] = __float_as_uint(pb[4 * SB]);
            }
#pragma unroll
            for (int mt = 0; mt < MT; mt++) {
                const float* pa = &As[buf][warp_m * (BM / 2) + mt * 16 + lr][k0 + lc];
                unsigned a0 = __float_as_uint(pa[0]);
                unsigned a1 = __float_as_uint(pa[8 * SA]);
                unsigned a2 = __float_as_uint(pa[4]);
                unsigned a3 = __float_as_uint(pa[8 * SA + 4]);
#pragma unroll
                for (int nt = 0; nt < 2; nt++)
                    mma_tf32(acc[mt][nt][0], acc[mt][nt][1], acc[mt][nt][2], acc[mt][nt][3],
                             a0, a1, a2, a3, b0[nt], b1[nt]);
            }
        }
        __syncthreads();
        buf ^= 1;
    }

#pragma unroll
    for (int mt = 0; mt < MT; mt++) {
#pragma unroll
        for (int nt = 0; nt < 2; nt++) {
            const int col = col0 + warp_n * 16 + nt * 8 + 2 * lc;
            const float bv0 = bias[col], bv1 = bias[col + 1];
#pragma unroll
            for (int h = 0; h < 2; h++) {
                const int row = row0 + warp_m * (BM / 2) + mt * 16 + lr + h * 8;
                const float rm = rowmask ? rowmask[row] : 1.f;
                float v0 = acc[mt][nt][2 * h + 0] + bv0;
                float v1 = acc[mt][nt][2 * h + 1] + bv1;
                if (act) { v0 = fmaxf(v0, 0.f); v1 = fmaxf(v1, 0.f); }
                Out[(size_t)row * N + col]     = v0 * rm;
                Out[(size_t)row * N + col + 1] = v1 * rm;
            }
        }
    }
}

template<int MT, int K>
__global__ __launch_bounds__(256)
void pgemm_kernel(const float* __restrict__ Aext, int Aid,
                  const float* __restrict__ W, const float* __restrict__ bias,
                  int Oid, int N, int act, const float* __restrict__ rowmask)
{
    const float* A = Aext ? Aext : scratch_ptr(Aid);
    pgemm_core<MT, K>(A, W, bias, scratch_ptr(Oid), N, act, rowmask,
                      blockIdx.y * MT * 32, blockIdx.x * 64);
}

// fused Q/K/V projections (MT=2: 192 blocks)
__global__ __launch_bounds__(256)
void qkv_kernel(const float* __restrict__ X,
                const float* __restrict__ Wq, const float* __restrict__ bq,
                const float* __restrict__ Wk, const float* __restrict__ bk,
                const float* __restrict__ Wv, const float* __restrict__ bv,
                const float* __restrict__ rowmask)
{
    const float* W; const float* b; float* Out;
    if (blockIdx.z == 0)      { W = Wq; b = bq; Out = g_Q; }
    else if (blockIdx.z == 1) { W = Wk; b = bk; Out = g_K; }
    else                      { W = Wv; b = bv; Out = g_V; }
    pgemm_core<2, DXD>(X, W, b, Out, DXD, 0, rowmask,
                       blockIdx.y * 64, blockIdx.x * 64);
}

// ---------------- fused Wo-GEMM(+mask) + residual + LayerNorm ----------------
#define SA2 20
#define SB2 260

__global__ __launch_bounds__(256)
void gemm_ln_kernel(const float* __restrict__ W,
                    const float* __restrict__ bias,
                    const float* __restrict__ rowmask,
                    const float* __restrict__ R,
                    const float* __restrict__ g, const float* __restrict__ beta)
{
    constexpr int K = DXD;
    constexpr int NK = K / 16;
    const float* A = g_att;
    float* Out = g_X1;

    __shared__ __align__(16) float As[2][16][SA2];
    __shared__ __align__(16) float Bs[2][16][SB2];

    const int tid  = threadIdx.x;
    const int lane = tid & 31;
    const int wid  = tid >> 5;
    const int lr = lane >> 2;
    const int lc = lane & 3;
    const int row0 = blockIdx.x * 16;

    const int ar = tid >> 2, aq = tid & 3;
    const bool aon = (tid < 64);
    const int bq = tid & 63;
    const int br_[4] = { (tid + 0) >> 6, (tid + 256) >> 6, (tid + 512) >> 6, (tid + 768) >> 6 };

    unsigned sA[2], sB[2][4];
#pragma unroll
    for (int bf = 0; bf < 2; bf++) {
        sA[bf] = (unsigned)__cvta_generic_to_shared(&As[bf][ar & 15][aq * 4]);
#pragma unroll
        for (int it = 0; it < 4; it++)
            sB[bf][it] = (unsigned)__cvta_generic_to_shared(&Bs[bf][br_[it]][bq * 4]);
    }

    if (aon) cp_async16(sA[0], &A[(size_t)(row0 + ar) * K + aq * 4]);
#pragma unroll
    for (int it = 0; it < 4; it++)
        cp_async16(sB[0][it], &W[(size_t)br_[it] * DXD + bq * 4]);
    CP_COMMIT();

    float acc[4][4];
#pragma unroll
    for (int nt = 0; nt < 4; nt++)
#pragma unroll
        for (int i = 0; i < 4; i++) acc[nt][i] = 0.f;

    int buf = 0;
#pragma unroll 2
    for (int ki = 0; ki < NK; ki++) {
        if (ki + 1 < NK) {
            const int kt = (ki + 1) * 16;
            if (aon) cp_async16(sA[buf ^ 1], &A[(size_t)(row0 + ar) * K + kt + aq * 4]);
#pragma unroll
            for (int it = 0; it < 4; it++)
                cp_async16(sB[buf ^ 1][it], &W[(size_t)(kt + br_[it]) * DXD + bq * 4]);
            CP_COMMIT();
            CP_WAIT(1);
        } else {
            CP_WAIT(0);
        }
        __syncthreads();

#pragma unroll
        for (int ks = 0; ks < 2; ks++) {
            const int k0 = ks * 8;
            const float* pa = &As[buf][lr][k0 + lc];
            unsigned a0 = __float_as_uint(pa[0]);
            unsigned a1 = __float_as_uint(pa[8 * SA2]);
            unsigned a2 = __float_as_uint(pa[4]);
            unsigned a3 = __float_as_uint(pa[8 * SA2 + 4]);
#pragma unroll
            for (int nt = 0; nt < 4; nt++) {
                const float* pb = &Bs[buf][k0 + lc][wid * 32 + nt * 8 + lr];
                unsigned b0 = __float_as_uint(pb[0]);
                unsigned b1 = __float_as_uint(pb[4 * SB2]);
                mma_tf32(acc[nt][0], acc[nt][1], acc[nt][2], acc[nt][3],
                         a0, a1, a2, a3, b0, b1);
            }
        }
        __syncthreads();
        buf ^= 1;
    }

    float (*S)[SB2] = Bs[0];
#pragma unroll
    for (int nt = 0; nt < 4; nt++) {
        const int col = wid * 32 + nt * 8 + 2 * lc;
#pragma unroll
        for (int h = 0; h < 2; h++) {
            S[lr + 8 * h][col]     = acc[nt][2 * h + 0];
            S[lr + 8 * h][col + 1] = acc[nt][2 * h + 1];
        }
    }
    __syncthreads();

#pragma unroll
    for (int rr = 0; rr < 2; rr++) {
        const int r = wid * 2 + rr;
        const int grow = row0 + r;
        const float rm = rowmask[grow];
        const int c0 = lane * 8;

        float vals[8];
        float sum = 0.f, sumsq = 0.f;
#pragma unroll
        for (int i = 0; i < 8; i++) {
            const int c = c0 + i;
            const float v = (S[r][c] + bias[c]) * rm + R[(size_t)grow * DXD + c];
            vals[i] = v;
            sum += v;
            sumsq = fmaf(v, v, sumsq);
        }
#pragma unroll
        for (int o = 16; o; o >>= 1) {
            sum   += __shfl_xor_sync(0xffffffffu, sum,   o);
            sumsq += __shfl_xor_sync(0xffffffffu, sumsq, o);
        }
        const float mu  = sum * (1.f / DXD);
        const float var = sumsq * (1.f / DXD) - mu * mu;
        const float inv = rsqrtf(var + EPSV);

        float o8[8];
#pragma unroll
        for (int i = 0; i < 8; i++)
            o8[i] = (vals[i] - mu) * inv * g[c0 + i] + beta[c0 + i];

        *(float4*)&Out[(size_t)grow * DXD + c0]     = make_float4(o8[0], o8[1], o8[2], o8[3]);
        *(float4*)&Out[(size_t)grow * DXD + c0 + 4] = make_float4(o8[4], o8[5], o8[6], o8[7]);
    }
}

// ---------------- attention: 2-stage cp.async, 2 query rows / block (measured best) ----------------
__global__ __launch_bounds__(256)
void attn_kernel(const float* __restrict__ e_add,
                 const float* __restrict__ e_mul,
                 const float* __restrict__ y_x_add,
                 const float* __restrict__ y_x_mul,
                 const float* __restrict__ node_mask)
{
    const int bp = blockIdx.x;            // 0..511
    const int b  = bp >> 7;
    const int i0 = (bp & 127) * 2;
    const int bi0 = b * NN + i0;
    const int d = threadIdx.x;

    __shared__ float s_ee[2][NN];
    __shared__ float s_on[NN];
    __shared__ __align__(16) float s_em[2][2][4][NN];   // [buf][row][jj][d] 16KB
    __shared__ __align__(16) float s_ea[2][2][4][NN];   // 16KB

    {
        const float mj  = node_mask[b * NN + d];
        const float mi0 = node_mask[b * NN + i0];
        const float mi1 = node_mask[b * NN + i0 + 1];
        s_on[d]    = (mj > 0.f) ? 1.f : 0.f;
        s_ee[0][d] = mi0 * mj;
        s_ee[1][d] = mi1 * mj;
    }
    __syncthreads();

    const float inv_sqrt_df = 0.1767766952966369f;
    const float q0 = g_Q[(size_t)bi0 * DXD + d] * inv_sqrt_df;
    const float q1 = g_Q[(size_t)(bi0 + 1) * DXD + d] * inv_sqrt_df;

    const float* gsrc[4];
    unsigned sd0[4], sd1[4];
#pragma unroll
    for (int c = 0; c < 4; c++) {
        const int id  = d + c * 256;
        const int arr = id >> 9;
        const int r   = (id >> 8) & 1;
        const int jj  = (id >> 6) & 3;
        const int seg = id & 63;
        const float* base = arr ? e_add : e_mul;
        gsrc[c] = base + ((size_t)(bi0 + r) * NN + jj) * DXD + seg * 4;
        float* s0p = arr ? &s_ea[0][r][jj][seg * 4] : &s_em[0][r][jj][seg * 4];
        float* s1p = arr ? &s_ea[1][r][jj][seg * 4] : &s_em[1][r][jj][seg * 4];
        sd0[c] = (unsigned)__cvta_generic_to_shared(s0p);
        sd1[c] = (unsigned)__cvta_generic_to_shared(s1p);
    }

#pragma unroll
    for (int c = 0; c < 4; c++) cp_async16(sd0[c], gsrc[c]);
    CP_COMMIT();

    const float* __restrict__ pk = g_K + (size_t)b * NN * DXD + d;
    const float* __restrict__ pv = g_V + (size_t)b * NN * DXD + d;

    float s0 = 0.f, a0 = 0.f, s1 = 0.f, a1 = 0.f;

    int buf = 0;
    for (int t = 0; t < 64; t++) {
        if (t < 63) {
            const size_t off = (size_t)(t + 1) * (4 * DXD);
#pragma unroll
            for (int c = 0; c < 4; c++)
                cp_async16(buf ? sd0[c] : sd1[c], gsrc[c] + off);
            CP_COMMIT();
            CP_WAIT(1);
        } else {
            CP_WAIT(0);
        }
        __syncthreads();

        const int j0 = t * 4;
#pragma unroll
        for (int jj = 0; jj < 4; jj++) {
            const int j = j0 + jj;
            const float kk = pk[(size_t)j * DXD];
            const float vv = pv[(size_t)j * DXD];
            const float on  = s_on[j];
            const float ee0 = s_ee[0][j];
            const float ee1 = s_ee[1][j];
            const float em0 = s_em[buf][0][jj][d];
            const float ea0 = s_ea[buf][0][jj][d];
            const float em1 = s_em[buf][1][jj][d];
            const float ea1 = s_ea[buf][1][jj][d];

            float y0 = fmaf(q0 * kk, fmaf(em0, ee0, 1.f), ea0 * ee0);
            float p0 = on * __expf(y0);
            s0 += p0;  a0 = fmaf(p0, vv, a0);

            float y1 = fmaf(q1 * kk, fmaf(em1, ee1, 1.f), ea1 * ee1);
            float p1 = on * __expf(y1);
            s1 += p1;  a1 = fmaf(p1, vv, a1);
        }
        __syncthreads();
        buf ^= 1;
    }

    const float ya = y_x_add[b * DXD + d];
    const float ym = y_x_mul[b * DXD + d] + 1.f;
    g_att[(size_t)bi0 * DXD + d]       = ya + ym * (a0 / s0);
    g_att[(size_t)(bi0 + 1) * DXD + d] = ya + ym * (a1 / s1);
}

// ---------------- single-pass layer norm over last dim (256) ----------------
__global__ __launch_bounds__(256)
void ln_kernel(int Aid, int Bid,
               const float* __restrict__ g, const float* __restrict__ beta,
               float* __restrict__ Out)
{
    const float* A = scratch_ptr(Aid);
    const float* B = scratch_ptr(Bid);

    __shared__ float red[16];

    const int row = blockIdx.x;
    const int t   = threadIdx.x;

    const float x = A[(size_t)row * DXD + t] + B[(size_t)row * DXD + t];
    float sx = x, sxx = x * x;
#pragma unroll
    for (int o = 16; o; o >>= 1) {
        sx  += __shfl_xor_sync(0xffffffffu, sx,  o);
        sxx += __shfl_xor_sync(0xffffffffu, sxx, o);
    }
    if ((t & 31) == 0) { red[t >> 5] = sx; red[8 + (t >> 5)] = sxx; }
    __syncthreads();
    sx  = red[0] + red[1] + red[2]  + red[3]  + red[4]  + red[5]  + red[6]  + red[7];
    sxx = red[8] + red[9] + red[10] + red[11] + red[12] + red[13] + red[14] + red[15];

    const float mu  = sx * (1.f / DXD);
    const float var = sxx * (1.f / DXD) - mu * mu;
    Out[(size_t)row * DXD + t] = (x - mu) * rsqrtf(var + EPSV) * g[t] + beta[t];
}

// ---------------- launch ----------------
extern "C" void kernel_launch(void* const* d_in, const int* in_sizes, int n_in,
                              void* d_out, int out_size)
{
    const float* X      = (const float*)d_in[0];
    const float* e_add  = (const float*)d_in[1];
    const float* e_mul  = (const float*)d_in[2];
    const float* yxa    = (const float*)d_in[3];
    const float* yxm    = (const float*)d_in[4];
    const float* nmask  = (const float*)d_in[5];
    const float* Wq     = (const float*)d_in[6];
    const float* bq     = (const float*)d_in[7];
    const float* Wk     = (const float*)d_in[8];
    const float* bk     = (const float*)d_in[9];
    const float* Wv     = (const float*)d_in[10];
    const float* bv     = (const float*)d_in[11];
    const float* Wo     = (const float*)d_in[12];
    const float* bo     = (const float*)d_in[13];
    const float* W1     = (const float*)d_in[14];
    const float* b1     = (const float*)d_in[15];
    const float* W2     = (const float*)d_in[16];
    const float* b2     = (const float*)d_in[17];
    const float* g1     = (const float*)d_in[18];
    const float* beta1  = (const float*)d_in[19];
    const float* g2     = (const float*)d_in[20];
    const float* b2ln   = (const float*)d_in[21];
    float* out          = (float*)d_out;

    // 1) fused QKV: MT=2 -> 192 blocks
    qkv_kernel<<<dim3(DXD / 64, MROWS / 64, 3), 256>>>(X, Wq, bq, Wk, bk, Wv, bv, nmask);

    // 2) attention (2-stage cp.async, 2 rows/block): 512 blocks
    attn_kernel<<<MROWS / 2, 256>>>(e_add, e_mul, yxa, yxm, nmask);

    // 3) fused: X1 = LN(X + mask*(att @ Wo + bo)). 64 blocks.
    gemm_ln_kernel<<<MROWS / 16, 256>>>(Wo, bo, nmask, X, g1, beta1);

    // 4) FFN1: relu(X1 @ W1 + b1): MT=2 -> 256 blocks
    pgemm_kernel<2, DXD><<<dim3(DFFD / 64, MROWS / 64), 256>>>(nullptr, 5, W1, b1, 6, DFFD, 1, nullptr);

    // 5) FFN2: ffn1 @ W2 + b2: 128 blocks, K=1024
    pgemm_kernel<1, DFFD><<<dim3(DXD / 64, MROWS / 32), 256>>>(nullptr, 6, W2, b2, 7, DXD, 0, nullptr);

    // 6) LN2 -> out
    ln_kernel<<<MROWS, 256>>>(5, 7, g2, b2ln, out);
}

// round 14
// speedup vs baseline: 1.3036x; 1.0133x over previous
#include <cuda_runtime.h>
#include <math.h>

#define BSZ 4
#define NN 256
#define DXD 256
#define DFFD 1024
#define EPSV 1e-5f
#define MROWS (BSZ*NN)   // 1024

// ---------------- scratch (allocation-free) ----------------
__device__ __align__(16) float g_Q   [MROWS*DXD];
__device__ __align__(16) float g_K   [MROWS*DXD];
__device__ __align__(16) float g_V   [MROWS*DXD];
__device__ __align__(16) float g_att [MROWS*DXD];
__device__ __align__(16) float g_X1  [MROWS*DXD];
__device__ __align__(16) float g_ffn1[MROWS*DFFD];
__device__ __align__(16) float g_ffn2[MROWS*DXD];

__device__ __forceinline__ float* scratch_ptr(int id) {
    switch (id) {
        case 0: return g_Q;
        case 1: return g_K;
        case 2: return g_V;
        case 3: return g_att;
        case 5: return g_X1;
        case 6: return g_ffn1;
        default: return g_ffn2;
    }
}

// ---------------- cp.async helpers ----------------
__device__ __forceinline__ void cp_async16(unsigned saddr, const void* gptr) {
    asm volatile("cp.async.ca.shared.global [%0], [%1], 16;" :: "r"(saddr), "l"(gptr));
}
#define CP_COMMIT() asm volatile("cp.async.commit_group;" ::: "memory")
#define CP_WAIT(n)  asm volatile("cp.async.wait_group %0;" :: "n"(n) : "memory")

// HMMA.TF32 reads operand regs as tf32 (bits [31:13]); raw fp32 bits = truncation.
__device__ __forceinline__ void mma_tf32(float& c0, float& c1, float& c2, float& c3,
                                         unsigned a0, unsigned a1, unsigned a2, unsigned a3,
                                         unsigned b0, unsigned b1)
{
    asm volatile(
        "mma.sync.aligned.m16n8k8.row.col.f32.tf32.tf32.f32 "
        "{%0,%1,%2,%3}, {%4,%5,%6,%7}, {%8,%9}, {%0,%1,%2,%3};"
        : "+f"(c0), "+f"(c1), "+f"(c2), "+f"(c3)
        : "r"(a0), "r"(a1), "r"(a2), "r"(a3), "r"(b0), "r"(b1));
}

// ---------------- tf32 GEMM, cp.async double-buffered, raw-bits fragments ----------------
#define SA 36
#define SB 68

template<int MT, int K>
__device__ __forceinline__ void pgemm_core(const float* __restrict__ A,
                                           const float* __restrict__ W,
                                           const float* __restrict__ bias,
                                           float* __restrict__ Out,
                                           int N, int act,
                                           const float* __restrict__ rowmask,
                                           int row0, int col0)
{
    constexpr int BM  = MT * 32;
    constexpr int AIT = BM / 32;
    constexpr int NK  = K / 32;

    __shared__ __align__(16) float As[2][BM][SA];
    __shared__ __align__(16) float Bs[2][32][SB];

    const int tid    = threadIdx.x;
    const int lane   = tid & 31;
    const int wid    = tid >> 5;
    const int warp_m = wid & 1;
    const int warp_n = wid >> 1;
    const int lr = lane >> 2;
    const int lc = lane & 3;

    int am_[AIT];
#pragma unroll
    for (int it = 0; it < AIT; it++) am_[it] = (tid + it * 256) >> 3;
    const int aq  = tid & 7;
    const int bk_[2] = { (tid + 0) >> 4, (tid + 256) >> 4 };
    const int bq  = tid & 15;

    unsigned sA[2][AIT], sB[2][2];
#pragma unroll
    for (int bf = 0; bf < 2; bf++) {
#pragma unroll
        for (int it = 0; it < AIT; it++)
            sA[bf][it] = (unsigned)__cvta_generic_to_shared(&As[bf][am_[it]][aq * 4]);
#pragma unroll
        for (int it = 0; it < 2; it++)
            sB[bf][it] = (unsigned)__cvta_generic_to_shared(&Bs[bf][bk_[it]][bq * 4]);
    }

#pragma unroll
    for (int it = 0; it < AIT; it++)
        cp_async16(sA[0][it], &A[(size_t)(row0 + am_[it]) * K + aq * 4]);
#pragma unroll
    for (int it = 0; it < 2; it++)
        cp_async16(sB[0][it], &W[(size_t)bk_[it] * N + col0 + bq * 4]);
    CP_COMMIT();

    float acc[MT][2][4];
#pragma unroll
    for (int mt = 0; mt < MT; mt++)
#pragma unroll
        for (int nt = 0; nt < 2; nt++)
#pragma unroll
            for (int i = 0; i < 4; i++) acc[mt][nt][i] = 0.f;

    int buf = 0;
#pragma unroll 2
    for (int ki = 0; ki < NK; ki++) {
        if (ki + 1 < NK) {
            const int kt = (ki + 1) * 32;
#pragma unroll
            for (int it = 0; it < AIT; it++)
                cp_async16(sA[buf ^ 1][it], &A[(size_t)(row0 + am_[it]) * K + kt + aq * 4]);
#pragma unroll
            for (int it = 0; it < 2; it++)
                cp_async16(sB[buf ^ 1][it], &W[(size_t)(kt + bk_[it]) * N + col0 + bq * 4]);
            CP_COMMIT();
            CP_WAIT(1);
        } else {
            CP_WAIT(0);
        }
        __syncthreads();

#pragma unroll
        for (int ks = 0; ks < 4; ks++) {
            const int k0 = ks * 8;
            unsigned b0[2], b1[2];
#pragma unroll
            for (int nt = 0; nt < 2; nt++) {
                const float* pb = &Bs[buf][k0 + lc][warp_n * 16 + nt * 8 + lr];
                b0[nt] = __float_as_uint(pb[0]);
                b1[nt] = __float_as_uint(pb[4 * SB]);
            }
#pragma unroll
            for (int mt = 0; mt < MT; mt++) {
                const float* pa = &As[buf][warp_m * (BM / 2) + mt * 16 + lr][k0 + lc];
                unsigned a0 = __float_as_uint(pa[0]);
                unsigned a1 = __float_as_uint(pa[8 * SA]);
                unsigned a2 = __float_as_uint(pa[4]);
                unsigned a3 = __float_as_uint(pa[8 * SA + 4]);
#pragma unroll
                for (int nt = 0; nt < 2; nt++)
                    mma_tf32(acc[mt][nt][0], acc[mt][nt][1], acc[mt][nt][2], acc[mt][nt][3],
                             a0, a1, a2, a3, b0[nt], b1[nt]);
            }
        }
        __syncthreads();
        buf ^= 1;
    }

#pragma unroll
    for (int mt = 0; mt < MT; mt++) {
#pragma unroll
        for (int nt = 0; nt < 2; nt++) {
            const int col = col0 + warp_n * 16 + nt * 8 + 2 * lc;
            const float bv0 = bias[col], bv1 = bias[col + 1];
#pragma unroll
            for (int h = 0; h < 2; h++) {
                const int row = row0 + warp_m * (BM / 2) + mt * 16 + lr + h * 8;
                const float rm = rowmask ? rowmask[row] : 1.f;
                float v0 = acc[mt][nt][2 * h + 0] + bv0;
                float v1 = acc[mt][nt][2 * h + 1] + bv1;
                if (act) { v0 = fmaxf(v0, 0.f); v1 = fmaxf(v1, 0.f); }
                Out[(size_t)row * N + col]     = v0 * rm;
                Out[(size_t)row * N + col + 1] = v1 * rm;
            }
        }
    }
}

template<int MT, int K>
__global__ __launch_bounds__(256)
void pgemm_kernel(const float* __restrict__ Aext, int Aid,
                  const float* __restrict__ W, const float* __restrict__ bias,
                  int Oid, int N, int act, const float* __restrict__ rowmask)
{
    const float* A = Aext ? Aext : scratch_ptr(Aid);
    pgemm_core<MT, K>(A, W, bias, scratch_ptr(Oid), N, act, rowmask,
                      blockIdx.y * MT * 32, blockIdx.x * 64);
}

// fused Q/K/V projections (MT=2: 192 blocks)
__global__ __launch_bounds__(256)
void qkv_kernel(const float* __restrict__ X,
                const float* __restrict__ Wq, const float* __restrict__ bq,
                const float* __restrict__ Wk, const float* __restrict__ bk,
                const float* __restrict__ Wv, const float* __restrict__ bv,
                const float* __restrict__ rowmask)
{
    const float* W; const float* b; float* Out;
    if (blockIdx.z == 0)      { W = Wq; b = bq; Out = g_Q; }
    else if (blockIdx.z == 1) { W = Wk; b = bk; Out = g_K; }
    else                      { W = Wv; b = bv; Out = g_V; }
    pgemm_core<2, DXD>(X, W, b, Out, DXD, 0, rowmask,
                       blockIdx.y * 64, blockIdx.x * 64);
}

// ---------------- fused Wo-GEMM(+mask) + residual + LayerNorm ----------------
#define SA2 20
#define SB2 260

__global__ __launch_bounds__(256)
void gemm_ln_kernel(const float* __restrict__ W,
                    const float* __restrict__ bias,
                    const float* __restrict__ rowmask,
                    const float* __restrict__ R,
                    const float* __restrict__ g, const float* __restrict__ beta)
{
    constexpr int K = DXD;
    constexpr int NK = K / 16;
    const float* A = g_att;
    float* Out = g_X1;

    __shared__ __align__(16) float As[2][16][SA2];
    __shared__ __align__(16) float Bs[2][16][SB2];

    const int tid  = threadIdx.x;
    const int lane = tid & 31;
    const int wid  = tid >> 5;
    const int lr = lane >> 2;
    const int lc = lane & 3;
    const int row0 = blockIdx.x * 16;

    const int ar = tid >> 2, aq = tid & 3;
    const bool aon = (tid < 64);
    const int bq = tid & 63;
    const int br_[4] = { (tid + 0) >> 6, (tid + 256) >> 6, (tid + 512) >> 6, (tid + 768) >> 6 };

    unsigned sA[2], sB[2][4];
#pragma unroll
    for (int bf = 0; bf < 2; bf++) {
        sA[bf] = (unsigned)__cvta_generic_to_shared(&As[bf][ar & 15][aq * 4]);
#pragma unroll
        for (int it = 0; it < 4; it++)
            sB[bf][it] = (unsigned)__cvta_generic_to_shared(&Bs[bf][br_[it]][bq * 4]);
    }

    if (aon) cp_async16(sA[0], &A[(size_t)(row0 + ar) * K + aq * 4]);
#pragma unroll
    for (int it = 0; it < 4; it++)
        cp_async16(sB[0][it], &W[(size_t)br_[it] * DXD + bq * 4]);
    CP_COMMIT();

    float acc[4][4];
#pragma unroll
    for (int nt = 0; nt < 4; nt++)
#pragma unroll
        for (int i = 0; i < 4; i++) acc[nt][i] = 0.f;

    int buf = 0;
#pragma unroll 2
    for (int ki = 0; ki < NK; ki++) {
        if (ki + 1 < NK) {
            const int kt = (ki + 1) * 16;
            if (aon) cp_async16(sA[buf ^ 1], &A[(size_t)(row0 + ar) * K + kt + aq * 4]);
#pragma unroll
            for (int it = 0; it < 4; it++)
                cp_async16(sB[buf ^ 1][it], &W[(size_t)(kt + br_[it]) * DXD + bq * 4]);
            CP_COMMIT();
            CP_WAIT(1);
        } else {
            CP_WAIT(0);
        }
        __syncthreads();

#pragma unroll
        for (int ks = 0; ks < 2; ks++) {
            const int k0 = ks * 8;
            const float* pa = &As[buf][lr][k0 + lc];
            unsigned a0 = __float_as_uint(pa[0]);
            unsigned a1 = __float_as_uint(pa[8 * SA2]);
            unsigned a2 = __float_as_uint(pa[4]);
            unsigned a3 = __float_as_uint(pa[8 * SA2 + 4]);
#pragma unroll
            for (int nt = 0; nt < 4; nt++) {
                const float* pb = &Bs[buf][k0 + lc][wid * 32 + nt * 8 + lr];
                unsigned b0 = __float_as_uint(pb[0]);
                unsigned b1 = __float_as_uint(pb[4 * SB2]);
                mma_tf32(acc[nt][0], acc[nt][1], acc[nt][2], acc[nt][3],
                         a0, a1, a2, a3, b0, b1);
            }
        }
        __syncthreads();
        buf ^= 1;
    }

    float (*S)[SB2] = Bs[0];
#pragma unroll
    for (int nt = 0; nt < 4; nt++) {
        const int col = wid * 32 + nt * 8 + 2 * lc;
#pragma unroll
        for (int h = 0; h < 2; h++) {
            S[lr + 8 * h][col]     = acc[nt][2 * h + 0];
            S[lr + 8 * h][col + 1] = acc[nt][2 * h + 1];
        }
    }
    __syncthreads();

#pragma unroll
    for (int rr = 0; rr < 2; rr++) {
        const int r = wid * 2 + rr;
        const int grow = row0 + r;
        const float rm = rowmask[grow];
        const int c0 = lane * 8;

        float vals[8];
        float sum = 0.f, sumsq = 0.f;
#pragma unroll
        for (int i = 0; i < 8; i++) {
            const int c = c0 + i;
            const float v = (S[r][c] + bias[c]) * rm + R[(size_t)grow * DXD + c];
            vals[i] = v;
            sum += v;
            sumsq = fmaf(v, v, sumsq);
        }
#pragma unroll
        for (int o = 16; o; o >>= 1) {
            sum   += __shfl_xor_sync(0xffffffffu, sum,   o);
            sumsq += __shfl_xor_sync(0xffffffffu, sumsq, o);
        }
        const float mu  = sum * (1.f / DXD);
        const float var = sumsq * (1.f / DXD) - mu * mu;
        const float inv = rsqrtf(var + EPSV);

        float o8[8];
#pragma unroll
        for (int i = 0; i < 8; i++)
            o8[i] = (vals[i] - mu) * inv * g[c0 + i] + beta[c0 + i];

        *(float4*)&Out[(size_t)grow * DXD + c0]     = make_float4(o8[0], o8[1], o8[2], o8[3]);
        *(float4*)&Out[(size_t)grow * DXD + c0 + 4] = make_float4(o8[4], o8[5], o8[6], o8[7]);
    }
}

// ---------------- attention: warp-autonomous 2-stage cp.async pipeline ----------------
// Warp w copies + consumes ONLY its own 32 channels -> no __syncthreads in the
// mainloop; pipeline synchronization is CP_WAIT + __syncwarp per warp.
__global__ __launch_bounds__(256)
void attn_kernel(const float* __restrict__ e_add,
                 const float* __restrict__ e_mul,
                 const float* __restrict__ y_x_add,
                 const float* __restrict__ y_x_mul,
                 const float* __restrict__ node_mask)
{
    const int bp = blockIdx.x;            // 0..511
    const int b  = bp >> 7;
    const int i0 = (bp & 127) * 2;
    const int bi0 = b * NN + i0;
    const int tid  = threadIdx.x;
    const int wd   = tid >> 5;
    const int lane = tid & 31;
    const int d    = tid;                 // channel

    __shared__ float s_ee[2][NN];
    __shared__ float s_on[NN];
    // [buf][warp][row][arr][jj][lane] : 2*8*2*2*4*32*4B = 32 KB
    __shared__ __align__(16) float s_e[2][8][2][2][4][32];

    {
        const float mj  = node_mask[b * NN + d];
        const float mi0 = node_mask[b * NN + i0];
        const float mi1 = node_mask[b * NN + i0 + 1];
        s_on[d]    = (mj > 0.f) ? 1.f : 0.f;
        s_ee[0][d] = mi0 * mj;
        s_ee[1][d] = mi1 * mj;
    }
    __syncthreads();   // masks ready (only block-wide sync in the kernel)

    const float inv_sqrt_df = 0.1767766952966369f;
    const float q0 = g_Q[(size_t)bi0 * DXD + d] * inv_sqrt_df;
    const float q1 = g_Q[(size_t)(bi0 + 1) * DXD + d] * inv_sqrt_df;

    // per-lane copy coords: 4 chunks of 16B; 128 chunks per warp tile
    // id = lane + c*32: piece = id&7 (16B piece of a 128B segment),
    // seg = id>>3: jj = seg&3, row = (seg>>2)&1, arr = seg>>3
    const float* gsrc[4];
    unsigned sd0[4], sd1[4];
#pragma unroll
    for (int c = 0; c < 4; c++) {
        const int id    = lane + c * 32;
        const int piece = id & 7;
        const int seg   = id >> 3;
        const int jj    = seg & 3;
        const int row   = (seg >> 2) & 1;
        const int arr   = seg >> 3;
        const float* base = arr ? e_add : e_mul;
        gsrc[c] = base + ((size_t)(bi0 + row) * NN + jj) * DXD + wd * 32 + piece * 4;
        sd0[c] = (unsigned)__cvta_generic_to_shared(&s_e[0][wd][row][arr][jj][piece * 4]);
        sd1[c] = (unsigned)__cvta_generic_to_shared(&s_e[1][wd][row][arr][jj][piece * 4]);
    }

#pragma unroll
    for (int c = 0; c < 4; c++) cp_async16(sd0[c], gsrc[c]);
    CP_COMMIT();

    const float* __restrict__ pk = g_K + (size_t)b * NN * DXD + d;
    const float* __restrict__ pv = g_V + (size_t)b * NN * DXD + d;

    float s0 = 0.f, a0 = 0.f, s1 = 0.f, a1 = 0.f;

    int buf = 0;
    for (int t = 0; t < 64; t++) {
        const int j0 = t * 4;

        // K/V loads issue before the pipeline wait -> L2 latency hides under it
        float kk[4], vv[4];
#pragma unroll
        for (int jj = 0; jj < 4; jj++) {
            kk[jj] = pk[(size_t)(j0 + jj) * DXD];
            vv[jj] = pv[(size_t)(j0 + jj) * DXD];
        }

        if (t < 63) {
            const size_t off = (size_t)(t + 1) * (4 * DXD);
#pragma unroll
            for (int c = 0; c < 4; c++)
                cp_async16(buf ? sd0[c] : sd1[c], gsrc[c] + off);
            CP_COMMIT();
            CP_WAIT(1);
        } else {
            CP_WAIT(0);
        }
        __syncwarp();   // cross-lane visibility of this warp's tile

#pragma unroll
        for (int jj = 0; jj < 4; jj++) {
            const int j = j0 + jj;
            const float on  = s_on[j];
            const float ee0 = s_ee[0][j];
            const float ee1 = s_ee[1][j];
            const float em0 = s_e[buf][wd][0][0][jj][lane];
            const float ea0 = s_e[buf][wd][0][1][jj][lane];
            const float em1 = s_e[buf][wd][1][0][jj][lane];
            const float ea1 = s_e[buf][wd][1][1][jj][lane];

            float y0 = fmaf(q0 * kk[jj], fmaf(em0, ee0, 1.f), ea0 * ee0);
            float p0 = on * __expf(y0);
            s0 += p0;  a0 = fmaf(p0, vv[jj], a0);

            float y1 = fmaf(q1 * kk[jj], fmaf(em1, ee1, 1.f), ea1 * ee1);
            float p1 = on * __expf(y1);
            s1 += p1;  a1 = fmaf(p1, vv[jj], a1);
        }
        __syncwarp();   // all lanes done reading before next overwrite
        buf ^= 1;
    }

    const float ya = y_x_add[b * DXD + d];
    const float ym = y_x_mul[b * DXD + d] + 1.f;
    g_att[(size_t)bi0 * DXD + d]       = ya + ym * (a0 / s0);
    g_att[(size_t)(bi0 + 1) * DXD + d] = ya + ym * (a1 / s1);
}

// ---------------- single-pass layer norm over last dim (256) ----------------
__global__ __launch_bounds__(256)
void ln_kernel(int Aid, int Bid,
               const float* __restrict__ g, const float* __restrict__ beta,
               float* __restrict__ Out)
{
    const float* A = scratch_ptr(Aid);
    const float* B = scratch_ptr(Bid);

    __shared__ float red[16];

    const int row = blockIdx.x;
    const int t   = threadIdx.x;

    const float x = A[(size_t)row * DXD + t] + B[(size_t)row * DXD + t];
    float sx = x, sxx = x * x;
#pragma unroll
    for (int o = 16; o; o >>= 1) {
        sx  += __shfl_xor_sync(0xffffffffu, sx,  o);
        sxx += __shfl_xor_sync(0xffffffffu, sxx, o);
    }
    if ((t & 31) == 0) { red[t >> 5] = sx; red[8 + (t >> 5)] = sxx; }
    __syncthreads();
    sx  = red[0] + red[1] + red[2]  + red[3]  + red[4]  + red[5]  + red[6]  + red[7];
    sxx = red[8] + red[9] + red[10] + red[11] + red[12] + red[13] + red[14] + red[15];

    const float mu  = sx * (1.f / DXD);
    const float var = sxx * (1.f / DXD) - mu * mu;
    Out[(size_t)row * DXD + t] = (x - mu) * rsqrtf(var + EPSV) * g[t] + beta[t];
}

// ---------------- launch ----------------
extern "C" void kernel_launch(void* const* d_in, const int* in_sizes, int n_in,
                              void* d_out, int out_size)
{
    const float* X      = (const float*)d_in[0];
    const float* e_add  = (const float*)d_in[1];
    const float* e_mul  = (const float*)d_in[2];
    const float* yxa    = (const float*)d_in[3];
    const float* yxm    = (const float*)d_in[4];
    const float* nmask  = (const float*)d_in[5];
    const float* Wq     = (const float*)d_in[6];
    const float* bq     = (const float*)d_in[7];
    const float* Wk     = (const float*)d_in[8];
    const float* bk     = (const float*)d_in[9];
    const float* Wv     = (const float*)d_in[10];
    const float* bv     = (const float*)d_in[11];
    const float* Wo     = (const float*)d_in[12];
    const float* bo     = (const float*)d_in[13];
    const float* W1     = (const float*)d_in[14];
    const float* b1     = (const float*)d_in[15];
    const float* W2     = (const float*)d_in[16];
    const float* b2     = (const float*)d_in[17];
    const float* g1     = (const float*)d_in[18];
    const float* beta1  = (const float*)d_in[19];
    const float* g2     = (const float*)d_in[20];
    const float* b2ln   = (const float*)d_in[21];
    float* out          = (float*)d_out;

    // 1) fused QKV: MT=2 -> 192 blocks
    qkv_kernel<<<dim3(DXD / 64, MROWS / 64, 3), 256>>>(X, Wq, bq, Wk, bk, Wv, bv, nmask);

    // 2) attention (warp-autonomous 2-stage cp.async): 512 blocks
    attn_kernel<<<MROWS / 2, 256>>>(e_add, e_mul, yxa, yxm, nmask);

    // 3) fused: X1 = LN(X + mask*(att @ Wo + bo)). 64 blocks.
    gemm_ln_kernel<<<MROWS / 16, 256>>>(Wo, bo, nmask, X, g1, beta1);

    // 4) FFN1: relu(X1 @ W1 + b1): MT=2 -> 256 blocks
    pgemm_kernel<2, DXD><<<dim3(DFFD / 64, MROWS / 64), 256>>>(nullptr, 5, W1, b1, 6, DFFD, 1, nullptr);

    // 5) FFN2: ffn1 @ W2 + b2: 128 blocks, K=1024
    pgemm_kernel<1, DFFD><<<dim3(DXD / 64, MROWS / 32), 256>>>(nullptr, 6, W2, b2, 7, DXD, 0, nullptr);

    // 6) LN2 -> out
    ln_kernel<<<MROWS, 256>>>(5, 7, g2, b2ln, out);
}